// round 11
// baseline (speedup 1.0000x reference)
#include <cuda_runtime.h>
#include <math.h>

#define D 4096
#define D4 1024
#define EPSF 1e-5f
#define EPS_VARF 1e-4f
#define PREP_BLOCKS 17

// ---------------- device scratch (static; no allocations) ----------------
__device__ __align__(16) float  g_ain[D];    // 1/(sqrt(var_in)+eps)
__device__ __align__(16) float  g_bin[D];    // -mean_in * ain
__device__ __align__(16) float  g_aout[D];   // 1/(sqrt(var_out)+eps)
__device__ __align__(16) float  g_bout[D];   // -mean_out * aout
__device__ __align__(16) float  g_mask[D];
__device__ __align__(16) double g_novel[D];
__device__ float g_scal[6]; // tau, A=(bu+bd)/2, B=(bu-bd)/2, gamma, beta_out, gamma_out
__device__ float g_invn;    // 1/||ema_out_dir||

// ---------------- fast math helpers ----------------
__device__ __forceinline__ float tanh_fast(float x) {
    float y;
    asm("tanh.approx.f32 %0, %1;" : "=f"(y) : "f"(x));
    return y;
}

__device__ __forceinline__ float gelu_f(float x) {
    float x2 = x * x;
    float arg = x * fmaf(0.035677408136300125f, x2, 0.7978845608028654f);
    float t = tanh_fast(arg);
    float h = 0.5f * x;
    return fmaf(h, t, h);
}

// ---------------- prep (parallel): block 0 = norm+scalars; blocks 1..16 = channel consts ----------------
__global__ void __launch_bounds__(256) prep_kernel(
    const float* __restrict__ ema_mean,
    const float* __restrict__ ema_sq,
    const float* __restrict__ ema_out_mean,
    const float* __restrict__ ema_out_sq,
    const float* __restrict__ ema_out_dir,
    const float* __restrict__ log_tau,
    const float* __restrict__ log_beta_up,
    const float* __restrict__ log_beta_dn,
    const float* __restrict__ log_gamma,
    const float* __restrict__ log_beta_out,
    const float* __restrict__ log_gamma_out)
{
    int b = blockIdx.x;
    int t = threadIdx.x;

    for (int i = b * 256 + t; i < D; i += PREP_BLOCKS * 256) g_novel[i] = 0.0;

    if (b == 0) {
        __shared__ float red[8];
        float s = 0.f;
        for (int c = t; c < D; c += 256) { float v = ema_out_dir[c]; s += v * v; }
        #pragma unroll
        for (int o = 16; o > 0; o >>= 1) s += __shfl_xor_sync(0xffffffffu, s, o);
        if ((t & 31) == 0) red[t >> 5] = s;
        __syncthreads();
        if (t == 0) {
            float tot = 0.f;
            #pragma unroll
            for (int i = 0; i < 8; i++) tot += red[i];
            g_invn = 1.0f / fmaxf(sqrtf(tot), 1e-12f);
            float bu = log1pf(expf(log_beta_up[0]));
            float bd = log1pf(expf(log_beta_dn[0]));
            g_scal[0] = expf(log_tau[0]);
            g_scal[1] = 0.5f * (bu + bd);            // A
            g_scal[2] = 0.5f * (bu - bd);            // B
            g_scal[3] = log1pf(expf(log_gamma[0]));  // gamma
            g_scal[4] = log1pf(expf(log_beta_out[0]));
            g_scal[5] = log1pf(expf(log_gamma_out[0]));
        }
    } else {
        int c = (b - 1) * 256 + t;  // blocks 1..16 cover 4096 channels
        float m   = ema_mean[c];
        float var = fmaxf(ema_sq[c] - m * m, EPS_VARF);
        float ai  = 1.0f / (sqrtf(var) + EPSF);
        g_ain[c] = ai;
        g_bin[c] = -m * ai;
        float mo   = ema_out_mean[c];
        float varo = fmaxf(ema_out_sq[c] - mo * mo, EPS_VARF);
        float ao   = 1.0f / (sqrtf(varo) + EPSF);
        g_aout[c] = ao;
        g_bout[c] = -mo * ao;
    }
}

// ---------------- pass 1: novelty ONLY (fp32 in-block, fp64 across blocks) ----------------
// grid: (4, rows/64), block 256. Thread owns one float4 column group over 64 rows.
// Pure stream: 1 LDG + 4 FFMA + 4 |z|-adds per float4. No shuffles, no row sums.
__global__ void __launch_bounds__(256) pass1_kernel(const float4* __restrict__ x4, int rows)
{
    int t = threadIdx.x;
    int c4 = blockIdx.x * 256 + t;
    int r0 = blockIdx.y * 64;

    const float4 ai = *(const float4*)&g_ain[c4 * 4];
    const float4 bi = *(const float4*)&g_bin[c4 * 4];

    float n0 = 0.f, n1 = 0.f, n2 = 0.f, n3 = 0.f;
    const float4* p = x4 + (size_t)r0 * D4 + c4;

    if (r0 + 64 <= rows) {
        for (int tile = 0; tile < 8; tile++) {
            int rb = tile * 8;
            float4 v[8];
            #pragma unroll
            for (int i = 0; i < 8; i++) v[i] = p[(size_t)(rb + i) * D4];
            #pragma unroll
            for (int i = 0; i < 8; i++) {
                n0 += fabsf(fmaf(v[i].x, ai.x, bi.x));
                n1 += fabsf(fmaf(v[i].y, ai.y, bi.y));
                n2 += fabsf(fmaf(v[i].z, ai.z, bi.z));
                n3 += fabsf(fmaf(v[i].w, ai.w, bi.w));
            }
        }
    } else {
        int nr = rows - r0; if (nr < 0) nr = 0;
        for (int r = 0; r < nr; r++) {
            float4 v = p[(size_t)r * D4];
            n0 += fabsf(fmaf(v.x, ai.x, bi.x));
            n1 += fabsf(fmaf(v.y, ai.y, bi.y));
            n2 += fabsf(fmaf(v.z, ai.z, bi.z));
            n3 += fabsf(fmaf(v.w, ai.w, bi.w));
        }
    }

    atomicAdd(&g_novel[c4 * 4 + 0], (double)n0);
    atomicAdd(&g_novel[c4 * 4 + 1], (double)n1);
    atomicAdd(&g_novel[c4 * 4 + 2], (double)n2);
    atomicAdd(&g_novel[c4 * 4 + 3], (double)n3);
}

// ---------------- top-k hard mask (exact rank, int64 keys) ----------------
__global__ void __launch_bounds__(512) mask_kernel(const int* __restrict__ kptr)
{
    __shared__ long long s[D];
    int t = threadIdx.x;
    for (int c = t; c < D; c += 512) s[c] = __double_as_longlong(g_novel[c]);
    __syncthreads();

    int k = kptr[0];
    if (k < 1 || k > D) {
        float kf = __int_as_float(k);
        if (kf >= 1.0f && kf <= (float)D) k = (int)kf;
        else if (k < 1) k = 1;
        else k = D;
    }

    int w = t >> 5, lane = t & 31;
    int d = blockIdx.x * 16 + w;       // 256*16 = 4096 channels
    long long sd = s[d];
    int cnt = 0;
    #pragma unroll 4
    for (int jj = 0; jj < D / 32; jj++) {
        int j = jj * 32 + lane;
        long long v = s[j];
        bool p = (v > sd) || (v == sd && j < d);
        cnt += __popc(__ballot_sync(0xffffffffu, p));
    }
    if (lane == 0) g_mask[d] = (cnt < k) ? 1.0f : 0.0f;
}

// ---------------- pass 2: full-row apply with in-block cos reduction ----------------
// block: 1024 threads = one full row of float4. grid = min(148, rows) blocks,
// each handling a contiguous balanced row range (single wave, 1 block/SM).
// Per row: gelu + s2/sd partials -> warp butterfly -> lane0 -> smem(parity
// double-buffered) -> ONE barrier -> each warp re-reduces 32 partials ->
// gc in-register -> gates -> evict-first store. Depth-2 row prefetch.
__global__ void __launch_bounds__(1024) apply3_kernel(const float4* __restrict__ x4,
                                                      float4* __restrict__ y4,
                                                      const float4* __restrict__ dir4,
                                                      int rows, int nblk)
{
    __shared__ float sm2[2][32];
    __shared__ float smd[2][32];

    int t = threadIdx.x;
    int w = t >> 5, lane = t & 31;

    const float tau = g_scal[0], A = g_scal[1], B = g_scal[2];
    const float gm = g_scal[3], bo = g_scal[4], go = g_scal[5];
    const float invn = g_invn;

    float4 c1 = *(const float4*)&g_ain[t * 4];
    float4 c2 = *(const float4*)&g_bin[t * 4];
    float4 c3 = *(const float4*)&g_aout[t * 4];
    float4 c4v = *(const float4*)&g_bout[t * 4];
    const float4 mk = *(const float4*)&g_mask[t * 4];
    const float4 ea = dir4[t];   // raw direction; invn folded into cos
    c1.x *= gm; c1.y *= gm; c1.z *= gm; c1.w *= gm;
    c2.x *= gm; c2.y *= gm; c2.z *= gm; c2.w *= gm;
    c3.x *= go; c3.y *= go; c3.z *= go; c3.w *= go;
    c4v.x *= go; c4v.y *= go; c4v.z *= go; c4v.w *= go;

    int b = blockIdx.x;
    int r0 = (int)(((long long)b * rows) / nblk);
    int r1 = (int)(((long long)(b + 1) * rows) / nblk);

    const float4* xp = x4 + t;
    float4* yp = y4 + t;

    float4 vb0, vb1;
    if (r0 < r1)     vb0 = xp[(size_t)r0 * D4];
    if (r0 + 1 < r1) vb1 = xp[(size_t)(r0 + 1) * D4];

    for (int r = r0; r < r1; r++) {
        float4 v = vb0;
        vb0 = vb1;
        if (r + 2 < r1) vb1 = xp[(size_t)(r + 2) * D4];

        float4 o;
        o.x = gelu_f(v.x); o.y = gelu_f(v.y); o.z = gelu_f(v.z); o.w = gelu_f(v.w);

        float s2 = fmaf(o.x, o.x, fmaf(o.y, o.y, fmaf(o.z, o.z, o.w * o.w)));
        float sd = fmaf(o.x, ea.x, fmaf(o.y, ea.y, fmaf(o.z, ea.z, o.w * ea.w)));
        #pragma unroll
        for (int off = 16; off > 0; off >>= 1) {
            float a2 = __shfl_xor_sync(0xffffffffu, s2, off);
            float ad = __shfl_xor_sync(0xffffffffu, sd, off);
            s2 += a2;
            sd += ad;
        }
        int par = r & 1;
        if (lane == 0) { sm2[par][w] = s2; smd[par][w] = sd; }
        __syncthreads();

        float p2 = sm2[par][lane];
        float pd = smd[par][lane];
        #pragma unroll
        for (int off = 16; off > 0; off >>= 1) {
            float a2 = __shfl_xor_sync(0xffffffffu, p2, off);
            float ad = __shfl_xor_sync(0xffffffffu, pd, off);
            p2 += a2;
            pd += ad;
        }
        float nrm = fmaxf(sqrtf(p2), 1e-12f);
        float cs = fminf(fmaxf(pd * invn / nrm, -1.0f), 1.0f);
        float gc = __expf(-tau * cs);

        float4 yv;
        {
            float t1 = tanh_fast(fmaf(v.x, c1.x, c2.x));
            float gin = fminf(fmaxf(fmaf(B, fabsf(t1), fmaf(A, t1, 1.0f)), 0.05f), 8.0f);
            float t2 = tanh_fast(fmaf(o.x, c3.x, c4v.x));
            float gout = fminf(fmaxf(fmaf(bo, t2, 1.0f), 0.1f), 5.0f);
            yv.x = o.x * fmaf(mk.x, gin * gout * gc - 1.0f, 1.0f);
        }
        {
            float t1 = tanh_fast(fmaf(v.y, c1.y, c2.y));
            float gin = fminf(fmaxf(fmaf(B, fabsf(t1), fmaf(A, t1, 1.0f)), 0.05f), 8.0f);
            float t2 = tanh_fast(fmaf(o.y, c3.y, c4v.y));
            float gout = fminf(fmaxf(fmaf(bo, t2, 1.0f), 0.1f), 5.0f);
            yv.y = o.y * fmaf(mk.y, gin * gout * gc - 1.0f, 1.0f);
        }
        {
            float t1 = tanh_fast(fmaf(v.z, c1.z, c2.z));
            float gin = fminf(fmaxf(fmaf(B, fabsf(t1), fmaf(A, t1, 1.0f)), 0.05f), 8.0f);
            float t2 = tanh_fast(fmaf(o.z, c3.z, c4v.z));
            float gout = fminf(fmaxf(fmaf(bo, t2, 1.0f), 0.1f), 5.0f);
            yv.z = o.z * fmaf(mk.z, gin * gout * gc - 1.0f, 1.0f);
        }
        {
            float t1 = tanh_fast(fmaf(v.w, c1.w, c2.w));
            float gin = fminf(fmaxf(fmaf(B, fabsf(t1), fmaf(A, t1, 1.0f)), 0.05f), 8.0f);
            float t2 = tanh_fast(fmaf(o.w, c3.w, c4v.w));
            float gout = fminf(fmaxf(fmaf(bo, t2, 1.0f), 0.1f), 5.0f);
            yv.w = o.w * fmaf(mk.w, gin * gout * gc - 1.0f, 1.0f);
        }
        __stcs(&yp[(size_t)r * D4], yv);
    }
}

// ---------------- launch ----------------
extern "C" void kernel_launch(void* const* d_in, const int* in_sizes, int n_in,
                              void* d_out, int out_size)
{
    (void)n_in; (void)out_size;
    const float* x             = (const float*)d_in[0];
    const float* log_tau       = (const float*)d_in[2];
    const float* log_beta_up   = (const float*)d_in[3];
    const float* log_beta_dn   = (const float*)d_in[4];
    const float* log_gamma     = (const float*)d_in[5];
    const float* log_beta_out  = (const float*)d_in[6];
    const float* log_gamma_out = (const float*)d_in[7];
    const float* ema_mean      = (const float*)d_in[9];
    const float* ema_sq        = (const float*)d_in[10];
    const float* ema_out_mean  = (const float*)d_in[11];
    const float* ema_out_sq    = (const float*)d_in[12];
    const float* ema_out_dir   = (const float*)d_in[13];
    const int*   kptr          = (const int*)d_in[14];

    int rows = in_sizes[0] / D; // 8192 for (4, 2048, 4096)

    prep_kernel<<<PREP_BLOCKS, 256>>>(ema_mean, ema_sq, ema_out_mean, ema_out_sq, ema_out_dir,
                                      log_tau, log_beta_up, log_beta_dn, log_gamma,
                                      log_beta_out, log_gamma_out);

    dim3 ng(4, (rows + 63) / 64);
    pass1_kernel<<<ng, 256>>>((const float4*)x, rows);

    mask_kernel<<<256, 512>>>(kptr);

    int nblk = rows < 148 ? rows : 148;
    apply3_kernel<<<nblk, 1024>>>((const float4*)x, (float4*)d_out,
                                  (const float4*)ema_out_dir, rows, nblk);
}